// round 13
// baseline (speedup 1.0000x reference)
#include <cuda_runtime.h>
#include <cuda_bf16.h>

#define N_NODES 50000
#define N_EDGES 800000
#define D_IN    128
#define D_OUT   64

// Scratch for h = x @ W (12.8 MB fp32; L2-resident during scatter)
__device__ float g_h[N_NODES * D_OUT];

// Packed fp32x2 FMA: d = a*b + d per 32-bit lane.
__device__ __forceinline__ void ffma2(unsigned long long& d,
                                      unsigned long long a,
                                      unsigned long long b) {
    asm("fma.rn.f32x2 %0, %1, %2, %0;" : "+l"(d) : "l"(a), "l"(b));
}

// ---------------------------------------------------------------------------
// Kernel 1: h = x @ W   (50000x128 @ 128x64)
// 256 threads, tile 128 rows x 64 cols. K in 8 chunks of 16, ping-pong Xs
// buffers with ONE barrier per pass:
//   pass p: LDG chunk p+1 -> regs -> STS into buf^1 (no live readers),
//           compute chunk p from buf, __syncthreads.
// Xs TRANSPOSED [k][row] stride 132 (528B, 16B-aligned): x-read per k is one
// conflict-free LDS.128 (4 distinct 16B, 8-lane broadcast). W reads are two
// conflict-free LDS.128 (8 distinct 16B each). No 4-way conflicts anywhere.
// Thread (rg,cg) = 4 rows x 8 cols, 16 f32x2 accumulators.
// smem = 32K (Ws) + 2*8.25K (Xs) = 49.6 KB; 3 CTAs/SM (launch_bounds 256,3).
// ---------------------------------------------------------------------------
#define KC 16            // k-chunk
#define XS_STRIDE 132    // floats per k-row (128 + 4 pad; 528 B, 16B-aligned)

__global__ __launch_bounds__(256, 3) void gemm_kernel(
    const float* __restrict__ x,
    const float* __restrict__ w,
    float* __restrict__ h)
{
    __shared__ __align__(16) float Ws[D_IN][D_OUT];          // 32 KB
    __shared__ __align__(16) float Xs[2][KC][XS_STRIDE];     // 16.5 KB

    const int t = threadIdx.x;
    const int row0 = blockIdx.x * 128;

    // Stage W once: 2048 float4, 8 per thread
    {
        const float4* w4 = (const float4*)w;
        #pragma unroll
        for (int i = 0; i < 8; i++) {
            const int idx = t + i * 256;        // float4 index into [128][16]
            const int kk = idx >> 4, cc = (idx & 15) * 4;
            *(float4*)&Ws[kk][cc] = w4[idx];
        }
    }

    // Loader mapping: 512 (row, k-quad) units, 2 per thread.
    // unit idx: row = idx>>2 (0..127), kq = idx&3 (k-quad within chunk).
    const int lrow0 = (t * 2) >> 2;          // rows for idx = 2t, 2t+1
    const int lkq0  = (t * 2) & 3;           // (2t even -> kq0 in {0,2})
    int g0 = row0 + lrow0;
    if (g0 > N_NODES - 1) g0 = N_NODES - 1;
    const float4* xr0 = (const float4*)(x + (size_t)g0 * D_IN);

    // Prologue: stage chunk 0 into buf 0
    {
        #pragma unroll
        for (int u = 0; u < 2; u++) {
            const int kq = lkq0 + u;         // both units share lrow0 (2t,2t+1)
            const float4 v = xr0[kq];        // pass 0: k offset = kq*4
            Xs[0][kq * 4 + 0][lrow0] = v.x;
            Xs[0][kq * 4 + 1][lrow0] = v.y;
            Xs[0][kq * 4 + 2][lrow0] = v.z;
            Xs[0][kq * 4 + 3][lrow0] = v.w;
        }
    }
    __syncthreads();

    const int rg = t >> 3;    // 0..31 -> rows rg*4 .. rg*4+3
    const int cg = t & 7;     // 0..7  -> cols cg*8 .. cg*8+7

    unsigned long long acc[4][4] = {};  // [row][col-pair] each = 2 fp32

    #pragma unroll 1
    for (int pass = 0; pass < D_IN / KC; pass++) {
        const int buf = pass & 1;

        // Stage chunk p+1 into buf^1 (no reader of buf^1 is live in pass p)
        if (pass + 1 < D_IN / KC) {
            float4 pv[2];
            #pragma unroll
            for (int u = 0; u < 2; u++)
                pv[u] = xr0[((pass + 1) * KC) / 4 + lkq0 + u];
            #pragma unroll
            for (int u = 0; u < 2; u++) {
                const int kq = lkq0 + u;
                Xs[buf ^ 1][kq * 4 + 0][lrow0] = pv[u].x;
                Xs[buf ^ 1][kq * 4 + 1][lrow0] = pv[u].y;
                Xs[buf ^ 1][kq * 4 + 2][lrow0] = pv[u].z;
                Xs[buf ^ 1][kq * 4 + 3][lrow0] = pv[u].w;
            }
        }

        // Compute chunk p
        #pragma unroll
        for (int k = 0; k < KC; k++) {
            const float4 xv = *(const float4*)&Xs[buf][k][rg * 4];
            const ulonglong2 wv0 = *(const ulonglong2*)&Ws[pass * KC + k][cg * 8];
            const ulonglong2 wv1 = *(const ulonglong2*)&Ws[pass * KC + k][cg * 8 + 4];
            const float xr[4] = {xv.x, xv.y, xv.z, xv.w};
            #pragma unroll
            for (int i = 0; i < 4; i++) {
                unsigned long long xp;
                asm("mov.b64 %0, {%1, %1};" : "=l"(xp) : "r"(__float_as_uint(xr[i])));
                ffma2(acc[i][0], xp, wv0.x);
                ffma2(acc[i][1], xp, wv0.y);
                ffma2(acc[i][2], xp, wv1.x);
                ffma2(acc[i][3], xp, wv1.y);
            }
        }
        __syncthreads();
    }

    // Store: 4 rows x 32 B per thread
    #pragma unroll
    for (int i = 0; i < 4; i++) {
        const int grow = row0 + rg * 4 + i;
        if (grow < N_NODES) {
            float* hp = h + (size_t)grow * D_OUT + cg * 8;
            ulonglong2 v0; v0.x = acc[i][0]; v0.y = acc[i][1];
            ulonglong2 v1; v1.x = acc[i][2]; v1.y = acc[i][3];
            *(ulonglong2*)(hp)     = v0;
            *(ulonglong2*)(hp + 4) = v1;
        }
    }
}

// ---------------------------------------------------------------------------
// Kernel 2: out[i][c] = bias[c]  (float4 broadcast; d_out is poisoned)
// ---------------------------------------------------------------------------
__global__ __launch_bounds__(256) void init_kernel(
    float* __restrict__ out,
    const float* __restrict__ bias)
{
    __shared__ float4 bs4[16];
    if (threadIdx.x < 16) bs4[threadIdx.x] = ((const float4*)bias)[threadIdx.x];
    __syncthreads();
    const int i = blockIdx.x * blockDim.x + threadIdx.x;   // float4 index
    if (i < N_NODES * D_OUT / 4) ((float4*)out)[i] = bs4[i & 15];
}

// ---------------------------------------------------------------------------
// Kernel 3: scatter-add (unchanged from the passing 61us kernel).
// 128 threads = 8 subgroups of 16 lanes; lane owns a float4 of dims.
// Sorted dst -> run-length accumulate in regs, atomics at run boundaries.
// ---------------------------------------------------------------------------
#define EPB 512

__device__ __forceinline__ void flush_acc(float* out, int node, int lane, float4 a)
{
    float* p = &out[(size_t)node * D_OUT + lane * 4];
    atomicAdd(p + 0, a.x);
    atomicAdd(p + 1, a.y);
    atomicAdd(p + 2, a.z);
    atomicAdd(p + 3, a.w);
}

__global__ __launch_bounds__(128) void scatter_kernel(
    const int*   __restrict__ src,
    const int*   __restrict__ dst,
    const float* __restrict__ vals,
    const float* __restrict__ h,
    float*       __restrict__ out)
{
    __shared__ __align__(16) int   s_src[EPB];
    __shared__ __align__(16) int   s_dst[EPB];
    __shared__ __align__(16) float s_val[EPB];

    const int t = threadIdx.x;
    const int e0 = blockIdx.x * EPB;
    int n = N_EDGES - e0;
    if (n > EPB) n = EPB;

    {
        const int i = t;
        const int e = e0 + i * 4;
        if (e + 3 < N_EDGES) {
            *(int4*)  &s_src[i * 4] = *(const int4*)  &src[e];
            *(int4*)  &s_dst[i * 4] = *(const int4*)  &dst[e];
            *(float4*)&s_val[i * 4] = *(const float4*)&vals[e];
        } else {
            #pragma unroll
            for (int j = 0; j < 4; j++) {
                if (e + j < N_EDGES) {
                    s_src[i * 4 + j] = src[e + j];
                    s_dst[i * 4 + j] = dst[e + j];
                    s_val[i * 4 + j] = vals[e + j];
                }
            }
        }
    }
    __syncthreads();

    const int sg   = t >> 4;
    const int lane = t & 15;
    const int lo = sg * (EPB / 8);
    int hi = lo + (EPB / 8);
    if (hi > n) hi = n;
    if (lo >= hi) return;

    int    d0 = s_dst[lo];
    float  v0 = s_val[lo];
    float4 h0 = *(const float4*)&h[(size_t)s_src[lo] * D_OUT + lane * 4];

    int cur = d0;
    float4 acc = make_float4(0.f, 0.f, 0.f, 0.f);

    for (int i = lo; i < hi - 1; i++) {
        const int    d1 = s_dst[i + 1];
        const float  v1 = s_val[i + 1];
        const float4 h1 = *(const float4*)&h[(size_t)s_src[i + 1] * D_OUT + lane * 4];

        if (d0 != cur) {
            flush_acc(out, cur, lane, acc);
            acc = make_float4(0.f, 0.f, 0.f, 0.f);
            cur = d0;
        }
        acc.x = fmaf(v0, h0.x, acc.x);
        acc.y = fmaf(v0, h0.y, acc.y);
        acc.z = fmaf(v0, h0.z, acc.z);
        acc.w = fmaf(v0, h0.w, acc.w);

        d0 = d1; v0 = v1; h0 = h1;
    }
    if (d0 != cur) {
        flush_acc(out, cur, lane, acc);
        acc = make_float4(0.f, 0.f, 0.f, 0.f);
        cur = d0;
    }
    acc.x = fmaf(v0, h0.x, acc.x);
    acc.y = fmaf(v0, h0.y, acc.y);
    acc.z = fmaf(v0, h0.z, acc.z);
    acc.w = fmaf(v0, h0.w, acc.w);
    flush_acc(out, cur, lane, acc);
}

// ---------------------------------------------------------------------------
// Launch.  Inputs: x, edge_src, edge_dst, edge_vals, weight, bias
// ---------------------------------------------------------------------------
extern "C" void kernel_launch(void* const* d_in, const int* in_sizes, int n_in,
                              void* d_out, int out_size)
{
    const float* x        = (const float*)d_in[0];
    const int*   edge_src = (const int*)  d_in[1];
    const int*   edge_dst = (const int*)  d_in[2];
    const float* edge_val = (const float*)d_in[3];
    const float* weight   = (const float*)d_in[4];
    const float* bias     = (const float*)d_in[5];
    float*       out      = (float*)d_out;

    float* h;
    cudaGetSymbolAddress((void**)&h, g_h);

    gemm_kernel<<<(N_NODES + 127) / 128, 256>>>(x, weight, h);

    init_kernel<<<(N_NODES * D_OUT / 4 + 255) / 256, 256>>>(out, bias);

    scatter_kernel<<<(N_EDGES + EPB - 1) / EPB, 128>>>(
        edge_src, edge_dst, edge_val, h, out);
}

// round 15
// speedup vs baseline: 1.1698x; 1.1698x over previous
#include <cuda_runtime.h>
#include <cuda_bf16.h>

#define N_NODES 50000
#define N_EDGES 800000
#define D_IN    128
#define D_OUT   64

typedef unsigned long long ull;

// Scratch for h = x @ W (12.8 MB fp32; L2-resident during scatter)
__device__ float g_h[N_NODES * D_OUT];

// Packed fp32x2 FMA: d = a*b + d per 32-bit lane.
__device__ __forceinline__ void ffma2(ull& d, ull a, ull b) {
    asm("fma.rn.f32x2 %0, %1, %2, %0;" : "+l"(d) : "l"(a), "l"(b));
}

__device__ __forceinline__ ull dup32(float f) {
    const unsigned u = __float_as_uint(f);
    return ((ull)u << 32) | u;
}
__device__ __forceinline__ ull pack2(float lo, float hi) {
    return ((ull)__float_as_uint(hi) << 32) | __float_as_uint(lo);
}

// ---------------------------------------------------------------------------
// Kernel 1: h = x @ W  (+ out = bias broadcast, fused)
// 64-row tiles, 256 threads, grid 782. NO packs in the inner loop:
//  - Xp[32][130] ull: Xp[p][k] = (x[p][k], x[p+32][k])  -> LDS.128 gives two
//    f32x2 row-pair operands directly.
//  - W2T[16][514] ull: W2T[c4][4k+j] = dup(w[k][4c4+j])  -> LDS.128 gives two
//    duplicated-column f32x2 operands. 257*16B group stride => quad index
//    (cg + 2k + j) mod 8: conflict-free.
// Thread (rg = t>>4, cg = t&15): rows {rg, rg+16, rg+32, rg+48},
// cols cg*4..+3; acc[pair][c] f32x2 (lo = row rg(+16), hi = row +32).
// Inner loop per 2k: 2 LDS.128(x) + 4 LDS.128(W) + 16 FFMA2 = 22 issues.
// One __syncthreads total. smem = 33.3K + 65.8K = 99.1 KB -> 2 CTAs/SM.
// ---------------------------------------------------------------------------
__global__ __launch_bounds__(256, 2) void gemm_kernel(
    const float* __restrict__ x,
    const float* __restrict__ w,
    const float* __restrict__ bias,
    float* __restrict__ h,
    float* __restrict__ out)
{
    __shared__ __align__(16) ull Xp[32][130];    // pairs (r, r+32), pad 2
    __shared__ __align__(16) ull W2T[16][514];   // [colgroup][k*4+j], pad 2

    const int t = threadIdx.x;
    const int row0 = blockIdx.x * 64;

    // --- Stage W duplicated: 2048 float4, 8 per thread ---
    {
        const float4* w4 = (const float4*)w;     // idx = k*16 + c4
        #pragma unroll
        for (int i = 0; i < 8; i++) {
            const int idx = t + i * 256;
            const int k = idx >> 4, c4 = idx & 15;
            const float4 v = w4[idx];
            ull* dst = &W2T[c4][k * 4];
            dst[0] = dup32(v.x); dst[1] = dup32(v.y);
            dst[2] = dup32(v.z); dst[3] = dup32(v.w);
        }
    }

    // --- Stage x pairs: 1024 (r32, kq) units, 4 per thread ---
    {
        const float4* x4 = (const float4*)x;     // row stride = 32 float4
        #pragma unroll
        for (int i = 0; i < 4; i++) {
            const int unit = t + i * 256;
            const int r32 = unit >> 5, kq = unit & 31;
            int ra = row0 + r32;      if (ra > N_NODES - 1) ra = N_NODES - 1;
            int rb = row0 + r32 + 32; if (rb > N_NODES - 1) rb = N_NODES - 1;
            const float4 va = x4[ra * 32 + kq];
            const float4 vb = x4[rb * 32 + kq];
            Xp[r32][kq * 4 + 0] = pack2(va.x, vb.x);
            Xp[r32][kq * 4 + 1] = pack2(va.y, vb.y);
            Xp[r32][kq * 4 + 2] = pack2(va.z, vb.z);
            Xp[r32][kq * 4 + 3] = pack2(va.w, vb.w);
        }
    }
    __syncthreads();

    const int rg = t >> 4;    // 0..15
    const int cg = t & 15;    // 0..15 -> cols cg*4..+3
    const ull* wt = &W2T[cg][0];

    ull acc[2][4] = {};       // [pair: rg / rg+16][col]; lo=row, hi=row+32

    #pragma unroll 8
    for (int k = 0; k < D_IN; k += 2) {
        const ulonglong2 xa = *(const ulonglong2*)&Xp[rg][k];        // k, k+1
        const ulonglong2 xb = *(const ulonglong2*)&Xp[rg + 16][k];
        const ulonglong2 w0 = *(const ulonglong2*)&wt[k * 4];        // k: c0,c1
        const ulonglong2 w1 = *(const ulonglong2*)&wt[k * 4 + 2];    // k: c2,c3
        const ulonglong2 w2 = *(const ulonglong2*)&wt[k * 4 + 4];    // k+1
        const ulonglong2 w3 = *(const ulonglong2*)&wt[k * 4 + 6];

        ffma2(acc[0][0], xa.x, w0.x); ffma2(acc[0][1], xa.x, w0.y);
        ffma2(acc[0][2], xa.x, w1.x); ffma2(acc[0][3], xa.x, w1.y);
        ffma2(acc[1][0], xb.x, w0.x); ffma2(acc[1][1], xb.x, w0.y);
        ffma2(acc[1][2], xb.x, w1.x); ffma2(acc[1][3], xb.x, w1.y);

        ffma2(acc[0][0], xa.y, w2.x); ffma2(acc[0][1], xa.y, w2.y);
        ffma2(acc[0][2], xa.y, w3.x); ffma2(acc[0][3], xa.y, w3.y);
        ffma2(acc[1][0], xb.y, w2.x); ffma2(acc[1][1], xb.y, w2.y);
        ffma2(acc[1][2], xb.y, w3.x); ffma2(acc[1][3], xb.y, w3.y);
    }

    // --- Epilogue: h rows + fused out = bias ---
    const float4 bias4 = ((const float4*)bias)[cg];
    #pragma unroll
    for (int pair = 0; pair < 2; pair++) {
        #pragma unroll
        for (int half = 0; half < 2; half++) {
            const int lrow = rg + pair * 16 + half * 32;
            const int grow = row0 + lrow;
            if (grow < N_NODES) {
                float4 v;
                const uint2 a0 = *(const uint2*)&acc[pair][0];
                const uint2 a1 = *(const uint2*)&acc[pair][1];
                const uint2 a2 = *(const uint2*)&acc[pair][2];
                const uint2 a3 = *(const uint2*)&acc[pair][3];
                v.x = __uint_as_float(half ? a0.y : a0.x);
                v.y = __uint_as_float(half ? a1.y : a1.x);
                v.z = __uint_as_float(half ? a2.y : a2.x);
                v.w = __uint_as_float(half ? a3.y : a3.x);
                *(float4*)&h[(size_t)grow * D_OUT + cg * 4]   = v;
                *(float4*)&out[(size_t)grow * D_OUT + cg * 4] = bias4;
            }
        }
    }
}

// ---------------------------------------------------------------------------
// Kernel 2: scatter-add (unchanged from the passing 61us kernel).
// 128 threads = 8 subgroups of 16 lanes; lane owns a float4 of dims.
// Sorted dst -> run-length accumulate in regs, atomics at run boundaries.
// ---------------------------------------------------------------------------
#define EPB 512

__device__ __forceinline__ void flush_acc(float* out, int node, int lane, float4 a)
{
    float* p = &out[(size_t)node * D_OUT + lane * 4];
    atomicAdd(p + 0, a.x);
    atomicAdd(p + 1, a.y);
    atomicAdd(p + 2, a.z);
    atomicAdd(p + 3, a.w);
}

__global__ __launch_bounds__(128) void scatter_kernel(
    const int*   __restrict__ src,
    const int*   __restrict__ dst,
    const float* __restrict__ vals,
    const float* __restrict__ h,
    float*       __restrict__ out)
{
    __shared__ __align__(16) int   s_src[EPB];
    __shared__ __align__(16) int   s_dst[EPB];
    __shared__ __align__(16) float s_val[EPB];

    const int t = threadIdx.x;
    const int e0 = blockIdx.x * EPB;
    int n = N_EDGES - e0;
    if (n > EPB) n = EPB;

    {
        const int i = t;
        const int e = e0 + i * 4;
        if (e + 3 < N_EDGES) {
            *(int4*)  &s_src[i * 4] = *(const int4*)  &src[e];
            *(int4*)  &s_dst[i * 4] = *(const int4*)  &dst[e];
            *(float4*)&s_val[i * 4] = *(const float4*)&vals[e];
        } else {
            #pragma unroll
            for (int j = 0; j < 4; j++) {
                if (e + j < N_EDGES) {
                    s_src[i * 4 + j] = src[e + j];
                    s_dst[i * 4 + j] = dst[e + j];
                    s_val[i * 4 + j] = vals[e + j];
                }
            }
        }
    }
    __syncthreads();

    const int sg   = t >> 4;
    const int lane = t & 15;
    const int lo = sg * (EPB / 8);
    int hi = lo + (EPB / 8);
    if (hi > n) hi = n;
    if (lo >= hi) return;

    int    d0 = s_dst[lo];
    float  v0 = s_val[lo];
    float4 h0 = *(const float4*)&h[(size_t)s_src[lo] * D_OUT + lane * 4];

    int cur = d0;
    float4 acc = make_float4(0.f, 0.f, 0.f, 0.f);

    for (int i = lo; i < hi - 1; i++) {
        const int    d1 = s_dst[i + 1];
        const float  v1 = s_val[i + 1];
        const float4 h1 = *(const float4*)&h[(size_t)s_src[i + 1] * D_OUT + lane * 4];

        if (d0 != cur) {
            flush_acc(out, cur, lane, acc);
            acc = make_float4(0.f, 0.f, 0.f, 0.f);
            cur = d0;
        }
        acc.x = fmaf(v0, h0.x, acc.x);
        acc.y = fmaf(v0, h0.y, acc.y);
        acc.z = fmaf(v0, h0.z, acc.z);
        acc.w = fmaf(v0, h0.w, acc.w);

        d0 = d1; v0 = v1; h0 = h1;
    }
    if (d0 != cur) {
        flush_acc(out, cur, lane, acc);
        acc = make_float4(0.f, 0.f, 0.f, 0.f);
        cur = d0;
    }
    acc.x = fmaf(v0, h0.x, acc.x);
    acc.y = fmaf(v0, h0.y, acc.y);
    acc.z = fmaf(v0, h0.z, acc.z);
    acc.w = fmaf(v0, h0.w, acc.w);
    flush_acc(out, cur, lane, acc);
}

// ---------------------------------------------------------------------------
// Launch.  Inputs: x, edge_src, edge_dst, edge_vals, weight, bias
// ---------------------------------------------------------------------------
extern "C" void kernel_launch(void* const* d_in, const int* in_sizes, int n_in,
                              void* d_out, int out_size)
{
    const float* x        = (const float*)d_in[0];
    const int*   edge_src = (const int*)  d_in[1];
    const int*   edge_dst = (const int*)  d_in[2];
    const float* edge_val = (const float*)d_in[3];
    const float* weight   = (const float*)d_in[4];
    const float* bias     = (const float*)d_in[5];
    float*       out      = (float*)d_out;

    float* h;
    cudaGetSymbolAddress((void**)&h, g_h);

    // GEMM + fused bias-init of out
    gemm_kernel<<<(N_NODES + 63) / 64, 256>>>(x, weight, bias, h, out);

    // Scatter: out[dst] += val * h[src]
    scatter_kernel<<<(N_EDGES + EPB - 1) / EPB, 128>>>(
        edge_src, edge_dst, edge_val, h, out);
}